// round 12
// baseline (speedup 1.0000x reference)
#include <cuda_runtime.h>
#include <cuda_bf16.h>

#define B_ 8
#define T_ 256
#define U_ 65
#define D_ 512
#define BTU_ (B_ * T_ * U_)
#define RSTRIDE 136              // floats per (b,t) row: 4 planes + pad
#define PAD 64                   // zero pad rows in front
#define RTOT 392                 // PAD + T + 72 back-pad rows

#define BIAS 10.0f
#define INV_LN2 1.4426950408889634f
#define LN2 0.6931471805599453f

// Plane-split row layout (RSTRIDE floats):
//   [  0.. 33] labelOdd : slot i = label(t, 2i-1), i=1..32; slots 0,33 stay 0
//   [ 34.. 66] blankEven: slot i = blank(t, 2i),   i=0..32
//   [ 67.. 99] blankOdd : slot i = blank(t, 2i+1), i=0..31; slot 32 stays 0
//   [100..132] labelEven: slot i = label(t, 2i),   i=0..32
//   [133..135] pad = 0
__device__ float g_probs[B_ * T_ * RSTRIDE];

__device__ __forceinline__ float ex2f(float x) {
    float y; asm("ex2.approx.ftz.f32 %0, %1;" : "=f"(y) : "f"(x)); return y;
}
__device__ __forceinline__ float lg2f(float x) {
    float y; asm("lg2.approx.ftz.f32 %0, %1;" : "=f"(y) : "f"(x)); return y;
}

// ---------------------------------------------------------------------------
// Kernel 1: per-row logsumexp over D=512 -> biased linear probs, plane-split.
// One warp per row; HBM-bound (proven ~42us shape).
// ---------------------------------------------------------------------------
__global__ void __launch_bounds__(256) lse_kernel(const float* __restrict__ logits,
                                                  const int* __restrict__ targets) {
    const int gw = (blockIdx.x * 256 + threadIdx.x) >> 5;
    const int lane = threadIdx.x & 31;
    if (gw >= BTU_) return;

    const float4* row4 = reinterpret_cast<const float4*>(logits + (size_t)gw * D_);
    const float4 v0 = row4[lane];
    const float4 v1 = row4[lane + 32];
    const float4 v2 = row4[lane + 64];
    const float4 v3 = row4[lane + 96];

    float m = v0.x;
    m = fmaxf(m, v0.y); m = fmaxf(m, v0.z); m = fmaxf(m, v0.w);
    m = fmaxf(m, v1.x); m = fmaxf(m, v1.y); m = fmaxf(m, v1.z); m = fmaxf(m, v1.w);
    m = fmaxf(m, v2.x); m = fmaxf(m, v2.y); m = fmaxf(m, v2.z); m = fmaxf(m, v2.w);
    m = fmaxf(m, v3.x); m = fmaxf(m, v3.y); m = fmaxf(m, v3.z); m = fmaxf(m, v3.w);
#pragma unroll
    for (int o = 16; o; o >>= 1) m = fmaxf(m, __shfl_xor_sync(0xffffffffu, m, o));

    float s = 0.f;
    s += __expf(v0.x - m) + __expf(v0.y - m) + __expf(v0.z - m) + __expf(v0.w - m);
    s += __expf(v1.x - m) + __expf(v1.y - m) + __expf(v1.z - m) + __expf(v1.w - m);
    s += __expf(v2.x - m) + __expf(v2.y - m) + __expf(v2.z - m) + __expf(v2.w - m);
    s += __expf(v3.x - m) + __expf(v3.y - m) + __expf(v3.z - m) + __expf(v3.w - m);
#pragma unroll
    for (int o = 16; o; o >>= 1) s += __shfl_xor_sync(0xffffffffu, s, o);

    const float lse = m + __logf(s);
    const float blankLogit = __shfl_sync(0xffffffffu, v3.w, 31);   // element 511

    if (lane == 0) {
        const int b = gw / (T_ * U_);
        const int rem = gw % (T_ * U_);
        const int t = rem / U_;
        const int u = rem % U_;
        const int lbl = (u < U_ - 1) ? targets[b * (U_ - 1) + u] : 0;
        const float labelLogit = __ldg(logits + (size_t)gw * D_ + lbl);
        const float pb = ex2f((blankLogit - lse) * INV_LN2 + BIAS);
        const float pl = ex2f((labelLogit - lse) * INV_LN2 + BIAS);
        const int base = (b * T_ + t) * RSTRIDE;
        if (u & 1) {
            g_probs[base + 0  + ((u + 1) >> 1)] = pl;   // labelOdd
            g_probs[base + 67 + ((u - 1) >> 1)] = pb;   // blankOdd
        } else {
            g_probs[base + 34  + (u >> 1)] = pb;        // blankEven
            g_probs[base + 100 + (u >> 1)] = pl;        // labelEven
        }
    }
}

// ---------------------------------------------------------------------------
// Kernel 2: linear-domain alpha DP, one CTA/batch. Two diagonals per macro
// step with a 1-deep register prefetch pipeline (sets a/b alternate). Renorm
// hoisted between 16-macro chunks. Maskless: zero padding is the mask.
// Lane l owns u={2l,2l+1}; lane 31 also u=64.
// ---------------------------------------------------------------------------
extern __shared__ float s_dyn[];

__global__ void __launch_bounds__(128) dp_kernel(const int* __restrict__ srcLen,
                                                 const int* __restrict__ tgtLen,
                                                 float* __restrict__ out) {
    const int b = blockIdx.x;
    const int tid = threadIdx.x;

    float* sP = s_dyn;   // [RTOT * RSTRIDE]

    {   // Zero pad rows front/back; copy valid rows (float4 contiguous).
        const float4 zr = make_float4(0.f, 0.f, 0.f, 0.f);
        float4* s4 = reinterpret_cast<float4*>(sP);
        const int rowQ = RSTRIDE / 4;                    // 34
        const int frontQ = PAD * rowQ;
        const int backStart = (PAD + T_) * rowQ;
        const int backQ = (RTOT - PAD - T_) * rowQ;
        for (int i = tid; i < frontQ; i += 128) s4[i] = zr;
        for (int i = tid; i < backQ; i += 128) s4[backStart + i] = zr;
        const float4* g4 = reinterpret_cast<const float4*>(g_probs + (size_t)b * T_ * RSTRIDE);
#pragma unroll 4
        for (int i = tid; i < T_ * rowQ; i += 128) s4[frontQ + i] = g4[i];
    }
    __syncthreads();
    if (tid >= 32) return;

    const int lane = tid;
    const int tE = srcLen[b] - 1;
    const int uE = tgtLen[b];
    const int dE = tE + uE;

    const int u0 = 2 * lane;

    float aE = (lane == 0) ? 1.0f : 0.0f;   // u = u0
    float aO = 0.0f;                        // u = u0+1
    float aX = 0.0f;                        // u = 64 (lane 31)
    float expShift = 0.0f;

    // Per-lane constant slot offsets; address(d) = sP + d*RSTRIDE + offset.
    const int oB0 = (PAD - 1 - u0) * RSTRIDE + 34 + lane;    // blank(t0-1, u0)
    const int oL0 = (PAD - u0) * RSTRIDE + lane;             // label(t0, u0-1); lane0 -> 0
    const int oB1 = (PAD - 2 - u0) * RSTRIDE + 67 + lane;    // blank(t0-2, u0+1)
    const int oL1 = (PAD - 1 - u0) * RSTRIDE + 100 + lane;   // label(t0-1, u0)
    const int oBx = (PAD - 65) * RSTRIDE + 66;               // blank(d-65, 64)
    const int oLx = (PAD - 64) * RSTRIDE + 32;               // label(d-64, 63)
    // Shifted coefficients (B1/L1 values at lane-1), used by the composition:
    const int oB1s = (PAD - u0) * RSTRIDE + 67 + lane - 1;       // lane0: junk x (L0p=0)
    const int oL1s = (PAD + 1 - u0) * RSTRIDE + 100 + lane - 1;  // lane0: 0-slot

    // Load the 14 raw values for the macro at diag (d, d+1), pd = sP + d*RSTRIDE.
#define LOADR(P, pd)                                                     \
    P##B0 = (pd)[oB0];            P##L0 = (pd)[oL0];                     \
    P##B1 = (pd)[oB1];            P##L1 = (pd)[oL1];                     \
    P##Bx = (pd)[oBx];            P##Lx = (pd)[oLx];                     \
    P##B1s = (pd)[oB1s];          P##L1s = (pd)[oL1s];                   \
    P##B0p = (pd)[oB0 + RSTRIDE]; P##L0p = (pd)[oL0 + RSTRIDE];          \
    P##B1p = (pd)[oB1 + RSTRIDE]; P##L1p = (pd)[oL1 + RSTRIDE];          \
    P##Bxp = (pd)[oBx + RSTRIDE]; P##Lxp = (pd)[oLx + RSTRIDE];

    // Composed 2-diagonal state update from raw set P.
#define STEPR(P)                                                         \
    {                                                                    \
        const float c1  = P##B0 * P##B0p;                                \
        const float c2  = fmaf(P##L0, P##B0p, P##B1s * P##L0p);          \
        const float c3  = P##L1s * P##L0p;                               \
        const float cO1 = P##B1 * P##B1p;                                \
        const float cO2 = fmaf(P##L1, P##B1p, P##B0 * P##L1p);           \
        const float cO3 = P##L0 * P##L1p;                                \
        const float cX1 = P##Bx * P##Bxp;                                \
        const float cX2 = fmaf(P##Lx, P##Bxp, P##B1 * P##Lxp);           \
        const float cX3 = P##L1 * P##Lxp;                                \
        const float shO = __shfl_up_sync(0xffffffffu, aO, 1);            \
        const float shE = __shfl_up_sync(0xffffffffu, aE, 1);            \
        const float nE = fmaf(aE, c1, fmaf(shO, c2, shE * c3));          \
        const float nO = fmaf(aO, cO1, fmaf(aE, cO2, shO * cO3));       \
        const float nX = fmaf(aX, cX1, fmaf(aO, cX2, aE * cX3));        \
        aE = nE; aO = nO; aX = nX;                                       \
    }

#define RENORM                                                                    \
    {                                                                             \
        float mval = fmaxf(aE, fmaxf(aO, aX));                                    \
        for (int o = 16; o; o >>= 1)                                              \
            mval = fmaxf(mval, __shfl_xor_sync(0xffffffffu, mval, o));            \
        const int e = ilogbf(mval);                                               \
        const float sc = __uint_as_float((unsigned)(127 - e) << 23);              \
        aE *= sc; aO *= sc; aX *= sc;                                             \
        expShift += (float)e;                                                     \
    }

    float aB0, aL0, aB1, aL1, aBx, aLx, aB1s, aL1s, aB0p, aL0p, aB1p, aL1p, aBxp, aLxp;
    float bB0, bL0, bB1, bL1, bBx, bLx, bB1s, bL1s, bB0p, bL0p, bB1p, bL1p, bBxp, bLxp;

    int d = 1;
    const float* pd = sP + RSTRIDE;          // sP + d*RSTRIDE at d=1
    if (dE & 1) {                            // consume one diag -> even remainder
        const float B0 = pd[oB0], L0 = pd[oL0];
        const float B1 = pd[oB1], L1 = pd[oL1];
        const float Bx = pd[oBx], Lx = pd[oLx];
        const float shO = __shfl_up_sync(0xffffffffu, aO, 1);
        const float nE = fmaf(aE, B0, shO * L0);
        const float nO = fmaf(aO, B1, aE * L1);
        const float nX = fmaf(aX, Bx, aO * Lx);
        aE = nE; aO = nO; aX = nX;
        d = 2; pd += RSTRIDE;
    }

    // Prologue: raws for the first macro (over-reads land in zero pads).
    LOADR(a, pd)

    // Chunks of 16 macros (32 diagonals); software-pipelined, branch-free body.
    while (d + 31 <= dE) {
#pragma unroll 2
        for (int k = 0; k < 16; k += 2) {
            LOADR(b, pd + 2 * RSTRIDE)     // prefetch next macro
            STEPR(a)                        // compute current
            pd += 2 * RSTRIDE;
            LOADR(a, pd + 2 * RSTRIDE)
            STEPR(b)
            pd += 2 * RSTRIDE;
        }
        d += 32;
        RENORM;
    }
    // Tail macros (< 16), pipeline invariant: set 'a' holds raws for pd.
    while (d + 1 <= dE) {
        STEPR(a)
        pd += 2 * RSTRIDE;
        d += 2;
        LOADR(a, pd)                        // may over-read; pads cover it
    }

    const bool ownE = (uE == u0);
    const bool ownO = (uE == u0 + 1);
    const bool ownX = (uE == 64) && (lane == 31);
    if (ownE || ownO || ownX) {
        float alphaF = ownX ? aX : (ownO ? aO : aE);
        if (dE == 0) alphaF = 1.0f;
        const int rb = (PAD + tE) * RSTRIDE;
        const float fb = (uE & 1) ? sP[rb + 67 + ((uE - 1) >> 1)]
                                  : sP[rb + 34 + (uE >> 1)];
        const float alpha_log2 = lg2f(alphaF) + expShift - BIAS * (float)dE;
        const float fb_log2 = lg2f(fb) - BIAS;
        out[b] = -LN2 * (alpha_log2 + fb_log2);
    }
#undef LOADR
#undef STEPR
#undef RENORM
}

// ---------------------------------------------------------------------------
extern "C" void kernel_launch(void* const* d_in, const int* in_sizes, int n_in,
                              void* d_out, int out_size) {
    const float* logits = (const float*)d_in[0];
    const int* targets = (const int*)d_in[1];
    const int* srcLen = (const int*)d_in[2];
    const int* tgtLen = (const int*)d_in[3];
    float* out = (float*)d_out;

    lse_kernel<<<BTU_ / 8, 256>>>(logits, targets);

    const int smemBytes = RTOT * RSTRIDE * (int)sizeof(float);  // 213248 B
    cudaFuncSetAttribute(dp_kernel, cudaFuncAttributeMaxDynamicSharedMemorySize, smemBytes);
    dp_kernel<<<B_, 128, smemBytes>>>(srcLen, tgtLen, out);
}

// round 13
// speedup vs baseline: 1.0372x; 1.0372x over previous
#include <cuda_runtime.h>
#include <cuda_bf16.h>

#define B_ 8
#define T_ 256
#define U_ 65
#define D_ 512
#define BTU_ (B_ * T_ * U_)
#define RSTRIDE 136              // floats per (b,t) row: 4 planes + pad
#define PAD 66                   // zero pad rows in front (smem only)
#define RTOT 392                 // PAD + T + 70 back-pad rows

#define BIAS 10.0f
#define INV_LN2 1.4426950408889634f
#define LN2 0.6931471805599453f

// Plane-split row layout (RSTRIDE floats):
//   [  0.. 33] labelOdd : slot i = label(t, 2i-1), i=1..32; slots 0,33 stay 0
//   [ 34.. 66] blankEven: slot i = blank(t, 2i),   i=0..32
//   [ 67.. 99] blankOdd : slot i = blank(t, 2i+1), i=0..31; slot 32 stays 0
//   [100..132] labelEven: slot i = label(t, 2i),   i=0..32
//   [133..135] pad = 0
__device__ float g_probs[B_ * T_ * RSTRIDE];

__device__ __forceinline__ float ex2f(float x) {
    float y; asm("ex2.approx.ftz.f32 %0, %1;" : "=f"(y) : "f"(x)); return y;
}
__device__ __forceinline__ float lg2f(float x) {
    float y; asm("lg2.approx.ftz.f32 %0, %1;" : "=f"(y) : "f"(x)); return y;
}

// ---------------------------------------------------------------------------
// Kernel 1: per-row logsumexp over D=512 -> biased linear probs, plane-split.
// One warp per row; HBM-bound (proven ~42us shape).
// ---------------------------------------------------------------------------
__global__ void __launch_bounds__(256) lse_kernel(const float* __restrict__ logits,
                                                  const int* __restrict__ targets) {
    const int gw = (blockIdx.x * 256 + threadIdx.x) >> 5;
    const int lane = threadIdx.x & 31;
    if (gw >= BTU_) return;

    const float4* row4 = reinterpret_cast<const float4*>(logits + (size_t)gw * D_);
    const float4 v0 = row4[lane];
    const float4 v1 = row4[lane + 32];
    const float4 v2 = row4[lane + 64];
    const float4 v3 = row4[lane + 96];

    float m = v0.x;
    m = fmaxf(m, v0.y); m = fmaxf(m, v0.z); m = fmaxf(m, v0.w);
    m = fmaxf(m, v1.x); m = fmaxf(m, v1.y); m = fmaxf(m, v1.z); m = fmaxf(m, v1.w);
    m = fmaxf(m, v2.x); m = fmaxf(m, v2.y); m = fmaxf(m, v2.z); m = fmaxf(m, v2.w);
    m = fmaxf(m, v3.x); m = fmaxf(m, v3.y); m = fmaxf(m, v3.z); m = fmaxf(m, v3.w);
#pragma unroll
    for (int o = 16; o; o >>= 1) m = fmaxf(m, __shfl_xor_sync(0xffffffffu, m, o));

    float s = 0.f;
    s += __expf(v0.x - m) + __expf(v0.y - m) + __expf(v0.z - m) + __expf(v0.w - m);
    s += __expf(v1.x - m) + __expf(v1.y - m) + __expf(v1.z - m) + __expf(v1.w - m);
    s += __expf(v2.x - m) + __expf(v2.y - m) + __expf(v2.z - m) + __expf(v2.w - m);
    s += __expf(v3.x - m) + __expf(v3.y - m) + __expf(v3.z - m) + __expf(v3.w - m);
#pragma unroll
    for (int o = 16; o; o >>= 1) s += __shfl_xor_sync(0xffffffffu, s, o);

    const float lse = m + __logf(s);
    const float blankLogit = __shfl_sync(0xffffffffu, v3.w, 31);   // element 511

    if (lane == 0) {
        const int b = gw / (T_ * U_);
        const int rem = gw % (T_ * U_);
        const int t = rem / U_;
        const int u = rem % U_;
        const int lbl = (u < U_ - 1) ? targets[b * (U_ - 1) + u] : 0;
        const float labelLogit = __ldg(logits + (size_t)gw * D_ + lbl);
        const float pb = ex2f((blankLogit - lse) * INV_LN2 + BIAS);
        const float pl = ex2f((labelLogit - lse) * INV_LN2 + BIAS);
        const int base = (b * T_ + t) * RSTRIDE;
        if (u & 1) {
            g_probs[base + 0  + ((u + 1) >> 1)] = pl;   // labelOdd
            g_probs[base + 67 + ((u - 1) >> 1)] = pb;   // blankOdd
        } else {
            g_probs[base + 34  + (u >> 1)] = pb;        // blankEven
            g_probs[base + 100 + (u >> 1)] = pl;        // labelEven
        }
    }
}

// ---------------------------------------------------------------------------
// Kernel 2: bidirectional linear-domain DP, one CTA/batch.
// Warp 0: alpha forward over diags 1..dM. Warp 1: beta backward over diags
// dE-1..dM. Combine on the cut diag dM: loss = sum_c alpha(c)*beta(c).
// Maskless: zero padding is the mask. Lane l owns u={2l,2l+1}; lane31 u=64.
// ---------------------------------------------------------------------------
extern __shared__ float s_dyn[];

__global__ void __launch_bounds__(128) dp_kernel(const int* __restrict__ srcLen,
                                                 const int* __restrict__ tgtLen,
                                                 float* __restrict__ out) {
    __shared__ float xch[97];    // beta state exchange: bE[32], bO[32], bX[32], shiftB

    const int b = blockIdx.x;
    const int tid = threadIdx.x;
    const int wid = tid >> 5;
    const int lane = tid & 31;

    float* sP = s_dyn;   // [RTOT * RSTRIDE]

    {   // Zero pad rows front/back; copy valid rows (float4 contiguous).
        const float4 zr = make_float4(0.f, 0.f, 0.f, 0.f);
        float4* s4 = reinterpret_cast<float4*>(sP);
        const int rowQ = RSTRIDE / 4;                    // 34
        const int frontQ = PAD * rowQ;
        const int backStart = (PAD + T_) * rowQ;
        const int backQ = (RTOT - PAD - T_) * rowQ;
        for (int i = tid; i < frontQ; i += 128) s4[i] = zr;
        for (int i = tid; i < backQ; i += 128) s4[backStart + i] = zr;
        const float4* g4 = reinterpret_cast<const float4*>(g_probs + (size_t)b * T_ * RSTRIDE);
#pragma unroll 4
        for (int i = tid; i < T_ * rowQ; i += 128) s4[frontQ + i] = g4[i];
    }
    __syncthreads();
    if (wid >= 2) return;

    const int tE = srcLen[b] - 1;
    const int uE = tgtLen[b];
    const int dE = tE + uE;
    const int dM = (dE + 1) >> 1;          // cut diagonal

    const int rb = (PAD + tE) * RSTRIDE;
    const float BtEuE = (uE & 1) ? sP[rb + 67 + ((uE - 1) >> 1)]
                                 : sP[rb + 34 + (uE >> 1)];

    if (dE == 0) {                          // degenerate: alpha(0,0)=1
        if (wid == 0 && lane == 0) out[b] = -LN2 * (lg2f(BtEuE) - BIAS);
        return;
    }

    const int u0 = 2 * lane;

#define RENORM3(x, y, z, shift)                                                   \
    {                                                                             \
        float mval = fmaxf(x, fmaxf(y, z));                                       \
        for (int o = 16; o; o >>= 1)                                              \
            mval = fmaxf(mval, __shfl_xor_sync(0xffffffffu, mval, o));            \
        const int e = ilogbf(mval);                                               \
        const float sc = __uint_as_float((unsigned)(127 - e) << 23);              \
        x *= sc; y *= sc; z *= sc;                                                \
        shift += (float)e;                                                        \
    }

    if (wid == 1) {
        // ---------------- beta backward: diag dE -> dM ----------------
        float bE = 0.f, bO = 0.f, bX = 0.f, shiftB = 0.f;
        if (uE == 64)      { if (lane == 31)        bX = BtEuE; }
        else if (uE & 1)   { if (lane == (uE >> 1)) bO = BtEuE; }
        else               { if (lane == (uE >> 1)) bE = BtEuE; }

        // Coefficient offsets at diag d (cell (t,u), t=d-u):
        const int oB0b = (PAD - u0) * RSTRIDE + 34 + lane;       // blank(t0, u0)
        const int oL0b = (PAD - u0) * RSTRIDE + 100 + lane;      // label(t0, u0)
        const int oB1b = (PAD - 1 - u0) * RSTRIDE + 67 + lane;   // blank(t1, u0+1)
        const int oL1b = (PAD - 1 - u0) * RSTRIDE + 1 + lane;    // label(t1, u0+1) (labelOdd slot l+1)
        const int oBxb = (PAD - 64) * RSTRIDE + 66;              // blank(d-64, 64)

        const float* pd = sP + (size_t)(dE - 1) * RSTRIDE;
        float cB0 = pd[oB0b], cL0 = pd[oL0b], cB1 = pd[oB1b], cL1 = pd[oL1b], cBx = pd[oBxb];

        int k = 0;
        for (int d = dE - 1; d >= dM; --d) {
            pd -= RSTRIDE;
            const float nB0 = pd[oB0b], nL0 = pd[oL0b];
            const float nB1 = pd[oB1b], nL1 = pd[oL1b], nBx = pd[oBxb];

            float sh = __shfl_down_sync(0xffffffffu, bE, 1);
            sh = (lane == 31) ? bX : sh;                     // u=63's right neighbor is u=64

            const float nE2 = fmaf(bE, cB0, bO * cL0);       // B(t0,u0)*b(t0+1,u0)+L(t0,u0)*b(t0,u0+1)
            const float nO2 = fmaf(bO, cB1, sh * cL1);
            const float nX2 = bX * cBx;                      // u=64: blank-only descent
            bE = nE2; bO = nO2; bX = nX2;

            cB0 = nB0; cL0 = nL0; cB1 = nB1; cL1 = nL1; cBx = nBx;

            if ((++k & 31) == 0) RENORM3(bE, bO, bX, shiftB)
        }

        xch[lane] = bE;
        xch[32 + lane] = bO;
        xch[64 + lane] = bX;
        if (lane == 0) xch[96] = shiftB;
        asm volatile("bar.sync 1, 64;" ::: "memory");
        return;
    }

    // ---------------- alpha forward: diag 1 -> dM (warp 0) ----------------
    float aE = (lane == 0) ? 1.0f : 0.0f;
    float aO = 0.f;
    float aX = 0.f;
    float shiftF = 0.f;

    const float* pB0 = sP + (PAD - u0) * RSTRIDE + 34 + lane;        // blank(t0-1, u0) @d=1
    const float* pL0 = sP + (PAD + 1 - u0) * RSTRIDE + 0 + lane;     // label(t0, u0-1)
    const float* pB1 = sP + (PAD - 1 - u0) * RSTRIDE + 67 + lane;    // blank(t0-2, u0+1)
    const float* pL1 = sP + (PAD - u0) * RSTRIDE + 100 + lane;       // label(t0-1, u0)
    const float* pBx = sP + (PAD + 1 - 65) * RSTRIDE + 66;           // blank(d-65, 64)
    const float* pLx = sP + (PAD + 1 - 64) * RSTRIDE + 32;           // label(d-64, 63)

    float cB0 = *pB0, cL0 = *pL0, cB1 = *pB1, cL1 = *pL1, cBx = *pBx, cLx = *pLx;

    for (int d = 1; d <= dM; ++d) {
        pB0 += RSTRIDE; pL0 += RSTRIDE; pB1 += RSTRIDE;
        pL1 += RSTRIDE; pBx += RSTRIDE; pLx += RSTRIDE;
        const float nB0 = *pB0, nL0 = *pL0, nB1 = *pB1;
        const float nL1 = *pL1, nBx = *pBx, nLx = *pLx;

        const float nbr = __shfl_up_sync(0xffffffffu, aO, 1);   // lane0: 0-slot kills it

        const float rE = fmaf(aE, cB0, nbr * cL0);
        const float rO = fmaf(aO, cB1, aE * cL1);
        const float rX = fmaf(aX, cBx, aO * cLx);
        aE = rE; aO = rO; aX = rX;

        cB0 = nB0; cL0 = nL0; cB1 = nB1; cL1 = nL1; cBx = nBx; cLx = nLx;

        if ((d & 31) == 0) RENORM3(aE, aO, aX, shiftF)
    }

    asm volatile("bar.sync 1, 64;" ::: "memory");

    // Cut combine: loss = sum over diag-dM cells of alpha*beta.
    float s = aE * xch[lane] + aO * xch[32 + lane] + aX * xch[64 + lane];
#pragma unroll
    for (int o = 16; o; o >>= 1) s += __shfl_xor_sync(0xffffffffu, s, o);

    if (lane == 0) {
        const float shiftB = xch[96];
        out[b] = -LN2 * (lg2f(s) + shiftF + shiftB - BIAS * (float)(dE + 1));
    }
#undef RENORM3
}

// ---------------------------------------------------------------------------
extern "C" void kernel_launch(void* const* d_in, const int* in_sizes, int n_in,
                              void* d_out, int out_size) {
    const float* logits = (const float*)d_in[0];
    const int* targets = (const int*)d_in[1];
    const int* srcLen = (const int*)d_in[2];
    const int* tgtLen = (const int*)d_in[3];
    float* out = (float*)d_out;

    lse_kernel<<<BTU_ / 8, 256>>>(logits, targets);

    const int smemBytes = RTOT * RSTRIDE * (int)sizeof(float);  // 213248 B
    cudaFuncSetAttribute(dp_kernel, cudaFuncAttributeMaxDynamicSharedMemorySize, smemBytes);
    dp_kernel<<<B_, 128, smemBytes>>>(srcLen, tgtLen, out);
}